// round 6
// baseline (speedup 1.0000x reference)
#include <cuda_runtime.h>

#define N_NODES 100000
#define NE      1000000
#define F       64
#define NBLK    ((N_NODES + 255) / 256)   // 391 scan blocks

// Scratch (allocation-free rule: __device__ globals), 16B-aligned.
__device__ __align__(16) int   g_cnt[N_NODES];      // in-degree (no self-loop)
__device__ __align__(16) int   g_off[N_NODES + 1];  // CSR offsets
__device__ __align__(16) int   g_cur[N_NODES];      // fill cursors
__device__ __align__(16) int   g_adj[NE];           // src sorted by dst
__device__ __align__(16) int   g_part[NBLK];        // block partial sums
__device__ __align__(16) int   g_poff[NBLK];        // block offsets
__device__ __align__(16) float g_dinv[N_NODES];
__device__ __align__(16) float g_hs [N_NODES * F];  // (X@W) * dinv[row]
__device__ __align__(16) float g_h2 [N_NODES * F];  // layer-1 output (post-relu)

// ---- packed f32x2 helpers (FFMA2 is PTX-only on sm_103a) ----
__device__ __forceinline__ unsigned long long pk2(float lo, float hi) {
    unsigned long long r;
    asm("mov.b64 %0, {%1, %2};" : "=l"(r) : "f"(lo), "f"(hi));
    return r;
}
__device__ __forceinline__ unsigned long long fma2(unsigned long long a,
                                                   unsigned long long b,
                                                   unsigned long long c) {
    unsigned long long r;
    asm("fma.rn.f32x2 %0, %1, %2, %3;" : "=l"(r) : "l"(a), "l"(b), "l"(c));
    return r;
}
__device__ __forceinline__ float2 upk2(unsigned long long v) {
    float2 f;
    asm("mov.b64 {%0, %1}, %2;" : "=f"(f.x), "=f"(f.y) : "l"(v));
    return f;
}

__global__ void k_zero_cnt() {
    int i = blockIdx.x * blockDim.x + threadIdx.x;
    if (i < N_NODES) g_cnt[i] = 0;
}

// 4 edges per thread (int4 loads), NE % 4 == 0.
__global__ void k_count(const int* __restrict__ dst) {
    int i = blockIdx.x * blockDim.x + threadIdx.x;
    if (i < NE / 4) {
        int4 d = ((const int4*)dst)[i];
        atomicAdd(&g_cnt[d.x], 1);
        atomicAdd(&g_cnt[d.y], 1);
        atomicAdd(&g_cnt[d.z], 1);
        atomicAdd(&g_cnt[d.w], 1);
    }
}

// Scan phase 1: per-block sums of 256 counts.
__global__ void k_scan1() {
    __shared__ int sh[256];
    int t = threadIdx.x;
    int i = blockIdx.x * 256 + t;
    sh[t] = (i < N_NODES) ? g_cnt[i] : 0;
    __syncthreads();
    for (int off = 128; off > 0; off >>= 1) {
        if (t < off) sh[t] += sh[t + off];
        __syncthreads();
    }
    if (t == 0) g_part[blockIdx.x] = sh[0];
}

// Scan phase 2: exclusive scan of NBLK (<=512) partials; shfl-based.
__global__ void k_scan2() {
    __shared__ int wsum[16];
    int t = threadIdx.x;            // 512 threads = 16 warps
    int lane = t & 31, w = t >> 5;
    int v = (t < NBLK) ? g_part[t] : 0;
    int s = v;
#pragma unroll
    for (int off = 1; off < 32; off <<= 1) {
        int u = __shfl_up_sync(0xffffffffu, s, off);
        if (lane >= off) s += u;
    }
    if (lane == 31) wsum[w] = s;
    __syncthreads();
    if (w == 0) {
        int ws = (lane < 16) ? wsum[lane] : 0;
#pragma unroll
        for (int off = 1; off < 16; off <<= 1) {
            int u = __shfl_up_sync(0xffffffffu, ws, off);
            if (lane >= off) ws += u;
        }
        if (lane < 16) wsum[lane] = ws;
    }
    __syncthreads();
    int incl = s + (w > 0 ? wsum[w - 1] : 0);
    if (t < NBLK) g_poff[t] = incl - v;
    if (t == 511) g_off[N_NODES] = incl;
}

// Scan phase 3: intra-block exclusive scan + base; writes off, cur, dinv.
__global__ void k_scan3() {
    __shared__ int sh[256];
    int t = threadIdx.x;
    int i = blockIdx.x * 256 + t;
    int v = (i < N_NODES) ? g_cnt[i] : 0;
    sh[t] = v;
    __syncthreads();
    for (int off = 1; off < 256; off <<= 1) {
        int u = (t >= off) ? sh[t - off] : 0;
        __syncthreads();
        sh[t] += u;
        __syncthreads();
    }
    if (i < N_NODES) {
        int o = g_poff[blockIdx.x] + sh[t] - v;
        g_off[i]  = o;
        g_cur[i]  = o;
        g_dinv[i] = rsqrtf((float)(v + 1));
    }
}

__global__ void k_fill(const int* __restrict__ src,
                       const int* __restrict__ dst) {
    int e = blockIdx.x * blockDim.x + threadIdx.x;
    if (e >= NE) return;
    int d = dst[e];
    int pos = atomicAdd(&g_cur[d], 1);
    g_adj[pos] = src[e];
}

// hs[r][c] = dinv[r] * sum_k X[r][k] * W[k][c].  Packed f32x2 mainloop.
__global__ void k_gemm_scale(const float* __restrict__ Xext,
                             const float* __restrict__ W, int useH2) {
    __shared__ float4 sW[64 * 16];
    __shared__ float  sX[64 * 68];

    const float* X = useH2 ? g_h2 : Xext;
    const int tid = threadIdx.x;
    const int rowBase = blockIdx.x * 64;

#pragma unroll
    for (int i = 0; i < 4; i++)
        sW[tid + i * 256] = ((const float4*)W)[tid + i * 256];

#pragma unroll
    for (int i = 0; i < 4; i++) {
        int v    = tid + i * 256;
        int row  = v >> 4;
        int col4 = v & 15;
        int gr   = rowBase + row;
        float4 x4 = make_float4(0.f, 0.f, 0.f, 0.f);
        if (gr < N_NODES) x4 = ((const float4*)(X + (size_t)gr * F))[col4];
        *(float4*)&sX[row * 68 + col4 * 4] = x4;
    }
    __syncthreads();

    const int tcol  = tid & 15;
    const int trow4 = tid >> 4;

    unsigned long long axy[4], azw[4];
    const unsigned long long z = pk2(0.f, 0.f);
#pragma unroll
    for (int j = 0; j < 4; j++) { axy[j] = z; azw[j] = z; }

#pragma unroll 16
    for (int k = 0; k < 64; k++) {
        float4 w = sW[k * 16 + tcol];
        unsigned long long wxy = pk2(w.x, w.y);
        unsigned long long wzw = pk2(w.z, w.w);
#pragma unroll
        for (int j = 0; j < 4; j++) {
            float xv = sX[(trow4 * 4 + j) * 68 + k];
            unsigned long long xx = pk2(xv, xv);
            axy[j] = fma2(xx, wxy, axy[j]);
            azw[j] = fma2(xx, wzw, azw[j]);
        }
    }

    const int gr0 = rowBase + trow4 * 4;
#pragma unroll
    for (int j = 0; j < 4; j++) {
        int r = gr0 + j;
        if (r < N_NODES) {
            float dv = g_dinv[r];
            float2 xy = upk2(axy[j]);
            float2 zw = upk2(azw[j]);
            ((float4*)(g_hs + (size_t)r * F))[tcol] =
                make_float4(xy.x * dv, xy.y * dv, zw.x * dv, zw.y * dv);
        }
    }
}

// Half-warp (16 lanes) per node; lane owns a float4 (4 cols). Unroll 8.
__global__ void k_gather(const float* __restrict__ bias,
                         float* __restrict__ outExt,
                         int doRelu, int toH2) {
    int gt   = blockIdx.x * blockDim.x + threadIdx.x;
    int node = gt >> 4;
    int lane = gt & 15;
    if (node >= N_NODES) return;

    const float4* hs4 = (const float4*)g_hs;
    int beg = g_off[node];
    int end = g_off[node + 1];

    float4 acc = hs4[(size_t)node * 16 + lane];  // self-loop

    int j = beg;
    for (; j + 8 <= end; j += 8) {
        int s0 = __ldg(&g_adj[j + 0]);
        int s1 = __ldg(&g_adj[j + 1]);
        int s2 = __ldg(&g_adj[j + 2]);
        int s3 = __ldg(&g_adj[j + 3]);
        int s4 = __ldg(&g_adj[j + 4]);
        int s5 = __ldg(&g_adj[j + 5]);
        int s6 = __ldg(&g_adj[j + 6]);
        int s7 = __ldg(&g_adj[j + 7]);
        float4 v0 = hs4[(size_t)s0 * 16 + lane];
        float4 v1 = hs4[(size_t)s1 * 16 + lane];
        float4 v2 = hs4[(size_t)s2 * 16 + lane];
        float4 v3 = hs4[(size_t)s3 * 16 + lane];
        float4 v4 = hs4[(size_t)s4 * 16 + lane];
        float4 v5 = hs4[(size_t)s5 * 16 + lane];
        float4 v6 = hs4[(size_t)s6 * 16 + lane];
        float4 v7 = hs4[(size_t)s7 * 16 + lane];
        acc.x += ((v0.x + v1.x) + (v2.x + v3.x)) + ((v4.x + v5.x) + (v6.x + v7.x));
        acc.y += ((v0.y + v1.y) + (v2.y + v3.y)) + ((v4.y + v5.y) + (v6.y + v7.y));
        acc.z += ((v0.z + v1.z) + (v2.z + v3.z)) + ((v4.z + v5.z) + (v6.z + v7.z));
        acc.w += ((v0.w + v1.w) + (v2.w + v3.w)) + ((v4.w + v5.w) + (v6.w + v7.w));
    }
    for (; j + 2 <= end; j += 2) {
        int s0 = __ldg(&g_adj[j + 0]);
        int s1 = __ldg(&g_adj[j + 1]);
        float4 v0 = hs4[(size_t)s0 * 16 + lane];
        float4 v1 = hs4[(size_t)s1 * 16 + lane];
        acc.x += v0.x + v1.x;
        acc.y += v0.y + v1.y;
        acc.z += v0.z + v1.z;
        acc.w += v0.w + v1.w;
    }
    if (j < end) {
        int s = __ldg(&g_adj[j]);
        float4 v = hs4[(size_t)s * 16 + lane];
        acc.x += v.x; acc.y += v.y; acc.z += v.z; acc.w += v.w;
    }

    float dv = g_dinv[node];
    float4 b = ((const float4*)bias)[lane];
    float4 o = make_float4(dv * acc.x + b.x, dv * acc.y + b.y,
                           dv * acc.z + b.z, dv * acc.w + b.w);
    if (doRelu) {
        o.x = fmaxf(o.x, 0.f); o.y = fmaxf(o.y, 0.f);
        o.z = fmaxf(o.z, 0.f); o.w = fmaxf(o.w, 0.f);
    }
    float4* dstp = toH2 ? (float4*)g_h2 : (float4*)outExt;
    dstp[(size_t)node * 16 + lane] = o;
}

extern "C" void kernel_launch(void* const* d_in, const int* in_sizes, int n_in,
                              void* d_out, int out_size) {
    const float* x  = (const float*)d_in[0];
    const int*   ei = (const int*)d_in[1];   // [2, NE] int32
    const float* W1 = (const float*)d_in[2];
    const float* b1 = (const float*)d_in[3];
    const float* W2 = (const float*)d_in[4];
    const float* b2 = (const float*)d_in[5];
    float*       out = (float*)d_out;

    const int* src = ei;
    const int* dst = ei + NE;

    const int T = 256;
    const int gN   = NBLK;                          // 391
    const int gE   = (NE + T - 1) / T;              // 3907
    const int gE4  = (NE / 4 + T - 1) / T;          // 977
    const int gGem = (N_NODES + 63) / 64;           // 1563
    const int gGat = (N_NODES * 16 + T - 1) / T;    // 6250 (16 thr/node)

    // CSR build + normalization (shared by both layers)
    k_zero_cnt<<<gN, T>>>();
    k_count<<<gE4, T>>>(dst);
    k_scan1<<<gN, T>>>();
    k_scan2<<<1, 512>>>();
    k_scan3<<<gN, T>>>();
    k_fill<<<gE, T>>>(src, dst);

    // Layer 1
    k_gemm_scale<<<gGem, T>>>(x, W1, 0);
    k_gather<<<gGat, T>>>(b1, out, /*relu=*/1, /*toH2=*/1);

    // Layer 2
    k_gemm_scale<<<gGem, T>>>(nullptr, W2, 1);
    k_gather<<<gGat, T>>>(b2, out, /*relu=*/0, /*toH2=*/0);
}

// round 7
// speedup vs baseline: 1.0349x; 1.0349x over previous
#include <cuda_runtime.h>

#define N_NODES 100000
#define NE      1000000
#define F       64
#define NBLK    ((N_NODES + 255) / 256)   // 391 scan blocks

// Scratch (allocation-free rule: __device__ globals), 16B-aligned.
__device__ __align__(16) int   g_cnt[N_NODES];      // in-degree (no self-loop)
__device__ __align__(16) int   g_off[N_NODES + 1];  // CSR offsets
__device__ __align__(16) int   g_cur[N_NODES];      // fill cursors
__device__ __align__(16) int   g_adj[NE];           // src sorted by dst
__device__ __align__(16) int   g_part[NBLK];        // block partial sums
__device__ __align__(16) float g_dinv[N_NODES];
__device__ __align__(16) float g_hs [N_NODES * F];  // (X@W) * dinv[row]
__device__ __align__(16) float g_h2 [N_NODES * F];  // layer-1 output (post-relu)

// ---- packed f32x2 helpers (FFMA2 is PTX-only on sm_103a) ----
__device__ __forceinline__ unsigned long long pk2(float lo, float hi) {
    unsigned long long r;
    asm("mov.b64 %0, {%1, %2};" : "=l"(r) : "f"(lo), "f"(hi));
    return r;
}
__device__ __forceinline__ unsigned long long fma2(unsigned long long a,
                                                   unsigned long long b,
                                                   unsigned long long c) {
    unsigned long long r;
    asm("fma.rn.f32x2 %0, %1, %2, %3;" : "=l"(r) : "l"(a), "l"(b), "l"(c));
    return r;
}
__device__ __forceinline__ float2 upk2(unsigned long long v) {
    float2 f;
    asm("mov.b64 {%0, %1}, %2;" : "=f"(f.x), "=f"(f.y) : "l"(v));
    return f;
}

// 4 edges per thread (int4 loads), NE % 4 == 0.
// g_cnt is zero on entry: zero-initialized at load, re-zeroed by k_scan3.
__global__ void k_count(const int* __restrict__ dst) {
    int i = blockIdx.x * blockDim.x + threadIdx.x;
    if (i < NE / 4) {
        int4 d = ((const int4*)dst)[i];
        atomicAdd(&g_cnt[d.x], 1);
        atomicAdd(&g_cnt[d.y], 1);
        atomicAdd(&g_cnt[d.z], 1);
        atomicAdd(&g_cnt[d.w], 1);
    }
}

// Scan phase 1: per-block sums of 256 counts.
__global__ void k_scan1() {
    __shared__ int sh[256];
    int t = threadIdx.x;
    int i = blockIdx.x * 256 + t;
    sh[t] = (i < N_NODES) ? g_cnt[i] : 0;
    __syncthreads();
    for (int off = 128; off > 0; off >>= 1) {
        if (t < off) sh[t] += sh[t + off];
        __syncthreads();
    }
    if (t == 0) g_part[blockIdx.x] = sh[0];
}

// Scan phase 3 (fused lookback): base = sum(part[0..bid)) computed in-block,
// then intra-block exclusive scan. Writes off, cur, dinv; self-cleans g_cnt.
__global__ void k_scan3() {
    __shared__ int sh[256];
    int t   = threadIdx.x;
    int bid = blockIdx.x;

    // base = sum of partials of preceding blocks
    int bs = 0;
    for (int i = t; i < bid; i += 256) bs += g_part[i];
    sh[t] = bs;
    __syncthreads();
    for (int off = 128; off > 0; off >>= 1) {
        if (t < off) sh[t] += sh[t + off];
        __syncthreads();
    }
    int base = sh[0];
    __syncthreads();

    int i = bid * 256 + t;
    int v = (i < N_NODES) ? g_cnt[i] : 0;
    if (i < N_NODES) g_cnt[i] = 0;  // self-clean for next graph replay
    sh[t] = v;
    __syncthreads();
    for (int off = 1; off < 256; off <<= 1) {
        int u = (t >= off) ? sh[t - off] : 0;
        __syncthreads();
        sh[t] += u;
        __syncthreads();
    }
    if (i < N_NODES) {
        int o = base + sh[t] - v;
        g_off[i]  = o;
        g_cur[i]  = o;
        g_dinv[i] = rsqrtf((float)(v + 1));
        if (i == N_NODES - 1) g_off[N_NODES] = o + v;
    }
}

__global__ void k_fill(const int* __restrict__ src,
                       const int* __restrict__ dst) {
    int e = blockIdx.x * blockDim.x + threadIdx.x;
    if (e >= NE) return;
    int d = dst[e];
    int pos = atomicAdd(&g_cur[d], 1);
    g_adj[pos] = src[e];
}

// hs[r][c] = dinv[r] * sum_k X[r][k] * W[k][c].
// 128-row x 64-col tile, 256 threads; thread = 4 rows x 8 cols (2 col-quads).
// f32x2 mainloop: 16 FFMA2 per k per thread.
__global__ void k_gemm_scale(const float* __restrict__ Xext,
                             const float* __restrict__ W, int useH2) {
    __shared__ float4 sW[64 * 16];      // sW[k*16 + c4] = W[k][4c4..+3]
    __shared__ float  sX[128 * 68];     // padded stride 68

    const float* X = useH2 ? g_h2 : Xext;
    const int tid = threadIdx.x;
    const int rowBase = blockIdx.x * 128;

#pragma unroll
    for (int i = 0; i < 4; i++)
        sW[tid + i * 256] = ((const float4*)W)[tid + i * 256];

#pragma unroll
    for (int i = 0; i < 8; i++) {
        int v    = tid + i * 256;      // float4 id, 0..2047
        int row  = v >> 4;
        int col4 = v & 15;
        int gr   = rowBase + row;
        float4 x4 = make_float4(0.f, 0.f, 0.f, 0.f);
        if (gr < N_NODES) x4 = ((const float4*)(X + (size_t)gr * F))[col4];
        *(float4*)&sX[row * 68 + col4 * 4] = x4;
    }
    __syncthreads();

    const int tcol = tid & 7;    // col quads tcol and tcol+8
    const int trow = tid >> 3;   // 0..31 -> rows trow*4..+3

    unsigned long long a0xy[4], a0zw[4], a1xy[4], a1zw[4];
    const unsigned long long z = pk2(0.f, 0.f);
#pragma unroll
    for (int j = 0; j < 4; j++) { a0xy[j] = z; a0zw[j] = z; a1xy[j] = z; a1zw[j] = z; }

#pragma unroll 16
    for (int k = 0; k < 64; k++) {
        float4 wa = sW[k * 16 + tcol];
        float4 wb = sW[k * 16 + tcol + 8];
        unsigned long long waxy = pk2(wa.x, wa.y);
        unsigned long long wazw = pk2(wa.z, wa.w);
        unsigned long long wbxy = pk2(wb.x, wb.y);
        unsigned long long wbzw = pk2(wb.z, wb.w);
#pragma unroll
        for (int j = 0; j < 4; j++) {
            float xv = sX[(trow * 4 + j) * 68 + k];
            unsigned long long xx = pk2(xv, xv);
            a0xy[j] = fma2(xx, waxy, a0xy[j]);
            a0zw[j] = fma2(xx, wazw, a0zw[j]);
            a1xy[j] = fma2(xx, wbxy, a1xy[j]);
            a1zw[j] = fma2(xx, wbzw, a1zw[j]);
        }
    }

    const int gr0 = rowBase + trow * 4;
#pragma unroll
    for (int j = 0; j < 4; j++) {
        int r = gr0 + j;
        if (r < N_NODES) {
            float dv = g_dinv[r];
            float2 xy0 = upk2(a0xy[j]);
            float2 zw0 = upk2(a0zw[j]);
            float2 xy1 = upk2(a1xy[j]);
            float2 zw1 = upk2(a1zw[j]);
            float4* o = (float4*)(g_hs + (size_t)r * F);
            o[tcol]     = make_float4(xy0.x * dv, xy0.y * dv, zw0.x * dv, zw0.y * dv);
            o[tcol + 8] = make_float4(xy1.x * dv, xy1.y * dv, zw1.x * dv, zw1.y * dv);
        }
    }
}

// Half-warp (16 lanes) per node; lane owns a float4 (4 cols). Unroll 8.
__global__ void k_gather(const float* __restrict__ bias,
                         float* __restrict__ outExt,
                         int doRelu, int toH2) {
    int gt   = blockIdx.x * blockDim.x + threadIdx.x;
    int node = gt >> 4;
    int lane = gt & 15;
    if (node >= N_NODES) return;

    const float4* hs4 = (const float4*)g_hs;
    int beg = g_off[node];
    int end = g_off[node + 1];

    float4 acc = hs4[(size_t)node * 16 + lane];  // self-loop

    int j = beg;
    for (; j + 8 <= end; j += 8) {
        int s0 = __ldg(&g_adj[j + 0]);
        int s1 = __ldg(&g_adj[j + 1]);
        int s2 = __ldg(&g_adj[j + 2]);
        int s3 = __ldg(&g_adj[j + 3]);
        int s4 = __ldg(&g_adj[j + 4]);
        int s5 = __ldg(&g_adj[j + 5]);
        int s6 = __ldg(&g_adj[j + 6]);
        int s7 = __ldg(&g_adj[j + 7]);
        float4 v0 = hs4[(size_t)s0 * 16 + lane];
        float4 v1 = hs4[(size_t)s1 * 16 + lane];
        float4 v2 = hs4[(size_t)s2 * 16 + lane];
        float4 v3 = hs4[(size_t)s3 * 16 + lane];
        float4 v4 = hs4[(size_t)s4 * 16 + lane];
        float4 v5 = hs4[(size_t)s5 * 16 + lane];
        float4 v6 = hs4[(size_t)s6 * 16 + lane];
        float4 v7 = hs4[(size_t)s7 * 16 + lane];
        acc.x += ((v0.x + v1.x) + (v2.x + v3.x)) + ((v4.x + v5.x) + (v6.x + v7.x));
        acc.y += ((v0.y + v1.y) + (v2.y + v3.y)) + ((v4.y + v5.y) + (v6.y + v7.y));
        acc.z += ((v0.z + v1.z) + (v2.z + v3.z)) + ((v4.z + v5.z) + (v6.z + v7.z));
        acc.w += ((v0.w + v1.w) + (v2.w + v3.w)) + ((v4.w + v5.w) + (v6.w + v7.w));
    }
    for (; j + 2 <= end; j += 2) {
        int s0 = __ldg(&g_adj[j + 0]);
        int s1 = __ldg(&g_adj[j + 1]);
        float4 v0 = hs4[(size_t)s0 * 16 + lane];
        float4 v1 = hs4[(size_t)s1 * 16 + lane];
        acc.x += v0.x + v1.x;
        acc.y += v0.y + v1.y;
        acc.z += v0.z + v1.z;
        acc.w += v0.w + v1.w;
    }
    if (j < end) {
        int s = __ldg(&g_adj[j]);
        float4 v = hs4[(size_t)s * 16 + lane];
        acc.x += v.x; acc.y += v.y; acc.z += v.z; acc.w += v.w;
    }

    float dv = g_dinv[node];
    float4 b = ((const float4*)bias)[lane];
    float4 o = make_float4(dv * acc.x + b.x, dv * acc.y + b.y,
                           dv * acc.z + b.z, dv * acc.w + b.w);
    if (doRelu) {
        o.x = fmaxf(o.x, 0.f); o.y = fmaxf(o.y, 0.f);
        o.z = fmaxf(o.z, 0.f); o.w = fmaxf(o.w, 0.f);
    }
    float4* dstp = toH2 ? (float4*)g_h2 : (float4*)outExt;
    dstp[(size_t)node * 16 + lane] = o;
}

extern "C" void kernel_launch(void* const* d_in, const int* in_sizes, int n_in,
                              void* d_out, int out_size) {
    const float* x  = (const float*)d_in[0];
    const int*   ei = (const int*)d_in[1];   // [2, NE] int32
    const float* W1 = (const float*)d_in[2];
    const float* b1 = (const float*)d_in[3];
    const float* W2 = (const float*)d_in[4];
    const float* b2 = (const float*)d_in[5];
    float*       out = (float*)d_out;

    const int* src = ei;
    const int* dst = ei + NE;

    const int T = 256;
    const int gN   = NBLK;                          // 391
    const int gE   = (NE + T - 1) / T;              // 3907
    const int gE4  = (NE / 4 + T - 1) / T;          // 977
    const int gGem = (N_NODES + 127) / 128;         // 782
    const int gGat = (N_NODES * 16 + T - 1) / T;    // 6250 (16 thr/node)

    // CSR build + normalization (shared by both layers)
    k_count<<<gE4, T>>>(dst);
    k_scan1<<<gN, T>>>();
    k_scan3<<<gN, T>>>();
    k_fill<<<gE, T>>>(src, dst);

    // Layer 1
    k_gemm_scale<<<gGem, T>>>(x, W1, 0);
    k_gather<<<gGat, T>>>(b1, out, /*relu=*/1, /*toH2=*/1);

    // Layer 2
    k_gemm_scale<<<gGem, T>>>(nullptr, W2, 1);
    k_gather<<<gGat, T>>>(b2, out, /*relu=*/0, /*toH2=*/0);
}